// round 16
// baseline (speedup 1.0000x reference)
#include <cuda_runtime.h>
#include <math.h>
#include <stdint.h>

#define NB 512
#define ND 256
#define NA 264
#define NM 16384
#define NH 8
#define NHD 33
#define NSPLIT 8
#define ATT_SC 0.17407765595569785f   // 1/sqrt(33)
#define L2E 1.4426950408889634f
#define CTXLD 272

typedef unsigned long long ull;

// ---------------- scratch ----------------
constexpr size_t SZ_MA   = (size_t)NM * NA;
constexpr size_t O_KH    = 0;
constexpr size_t O_VH    = O_KH + SZ_MA;
constexpr size_t O_PO    = O_VH + SZ_MA;
constexpr size_t O_NEWK  = O_PO + (size_t)NSPLIT * NB * NA;
constexpr size_t O_NEWV  = O_NEWK + (size_t)NB * ND;
constexpr size_t O_QH    = O_NEWV + (size_t)NB * ND;        // QH, NEWKH, NEWVH contiguous
constexpr size_t O_NEWKH = O_QH + (size_t)NB * NA;
constexpr size_t O_NEWVH = O_NEWKH + (size_t)NB * NA;
constexpr size_t O_FOLD  = O_NEWVH + (size_t)NB * NA;       // [792][256] fold^T
constexpr size_t O_WKT   = O_FOLD + (size_t)3 * NA * ND;
constexpr size_t O_WVT   = O_WKT + (size_t)ND * ND;
constexpr size_t O_WCOT  = O_WVT + (size_t)ND * ND;         // [256][272]
constexpr size_t O_CTX   = O_WCOT + (size_t)ND * CTXLD;
constexpr size_t O_BPQ   = O_CTX + (size_t)NB * CTXLD;
constexpr size_t O_BCO   = O_BPQ + 3 * NA;
constexpr size_t O_FN2   = O_BCO + ND;
constexpr size_t O_GN2   = O_FN2 + NB;
constexpr size_t O_KN2   = O_GN2 + NB;
constexpr size_t O_MIND2 = O_KN2 + NM;
constexpr size_t O_SURP  = O_MIND2 + NB;
constexpr size_t O_PM    = O_SURP + NB;
constexpr size_t O_PL    = O_PM + (size_t)NSPLIT * NB * NH;
constexpr size_t O_END   = O_PL + (size_t)NSPLIT * NB * NH;

__device__ float g_fbuf[O_END];

#define IB_MEMZ  0
#define IB_NW    512
#define IB_WSLOT 520
#define IB_WB    1036
#define IB_WFIN  1552
__device__ int g_ibuf[2072];

// ---------------- helpers ----------------
__device__ __forceinline__ unsigned fenc(float f) {
    unsigned b = __float_as_uint(f);
    return b ^ (unsigned)(((int)b >> 31) | 0x80000000);
}
__device__ __forceinline__ float fdec(unsigned e) {
    unsigned b = (e & 0x80000000u) ? (e ^ 0x80000000u) : ~e;
    return __uint_as_float(b);
}
__device__ __forceinline__ unsigned f2tf(float x) {
    unsigned r;
    asm("cvt.rna.tf32.f32 %0, %1;" : "=r"(r) : "f"(x));
    return r;
}
__device__ __forceinline__ void mma_tf32(float d[4], const unsigned a[4], const unsigned b[2]) {
    asm volatile("mma.sync.aligned.m16n8k8.row.col.f32.tf32.tf32.f32 "
                 "{%0,%1,%2,%3}, {%4,%5,%6,%7}, {%8,%9}, {%0,%1,%2,%3};\n"
                 : "+f"(d[0]), "+f"(d[1]), "+f"(d[2]), "+f"(d[3])
                 : "r"(a[0]), "r"(a[1]), "r"(a[2]), "r"(a[3]), "r"(b[0]), "r"(b[1]));
}
#define UF(x) __uint_as_float(x)
#define FU(x) __float_as_uint(x)

// ---------------- small kernels ----------------
__global__ void init_kernel(unsigned* mind2) {
    int i = blockIdx.x * 256 + threadIdx.x;
    if (i < NB) mind2[i] = 0xFFFFFFFFu;
}
__global__ void zero_kernel(float* p, int n) {
    int i = blockIdx.x * 256 + threadIdx.x;
    if (i < n) p[i] = 0.f;
}
__global__ void rownorm2_kernel(const float* __restrict__ X, float* __restrict__ out) {
    int row = blockIdx.x;
    int t = threadIdx.x;
    float v = X[(size_t)row * ND + t];
    float s = v * v;
    #pragma unroll
    for (int o = 16; o; o >>= 1) s += __shfl_xor_sync(0xffffffffu, s, o);
    __shared__ float ws[8];
    if ((t & 31) == 0) ws[t >> 5] = s;
    __syncthreads();
    if (t == 0) {
        float tot = 0.f;
        #pragma unroll
        for (int i = 0; i < 8; i++) tot += ws[i];
        out[row] = tot;
    }
}
__global__ void surprise_kernel(const unsigned* __restrict__ mind2,
                                const float* __restrict__ gn2,
                                float* __restrict__ surp, int* __restrict__ memz) {
    int b = blockIdx.x * 256 + threadIdx.x;
    if (b < NB) {
        float md2 = fdec(mind2[b]);
        if (md2 < 0.f) md2 = 0.f;
        float s = sqrtf(gn2[b]) * sqrtf(md2);
        surp[b] = s;
        memz[b] = (s > 0.1f) ? 1 : 0;
    }
}
__global__ void transpose_kernel(const float* __restrict__ src, float* __restrict__ dst,
                                 int R, int C, int ldd) {
    __shared__ float tile[32][33];
    int x = blockIdx.x * 32 + threadIdx.x;
    int y = blockIdx.y * 32 + threadIdx.y;
    #pragma unroll
    for (int j = 0; j < 32; j += 8)
        if (y + j < R && x < C) tile[threadIdx.y + j][threadIdx.x] = src[(size_t)(y + j) * C + x];
    __syncthreads();
    int x2 = blockIdx.y * 32 + threadIdx.x;
    int y2 = blockIdx.x * 32 + threadIdx.y;
    #pragma unroll
    for (int j = 0; j < 32; j += 8)
        if (y2 + j < C && x2 < R) dst[(size_t)(y2 + j) * ldd + x2] = tile[threadIdx.x][threadIdx.y + j];
}

// ---------------- legacy SGEMM with TRANSPOSED store ----------------
__global__ __launch_bounds__(256)
void gemmT_kernel(const float* __restrict__ A, const float* __restrict__ Bm,
                  float* __restrict__ Ct,
                  int M, int N, int K, int lda, int ldb, int ldc) {
    __shared__ __align__(16) float As[16][68];
    __shared__ __align__(16) float Bs[16][68];
    int tx = threadIdx.x, ty = threadIdx.y;
    int t = ty * 16 + tx;
    int m0 = blockIdx.y * 64, n0 = blockIdx.x * 64;
    float acc[4][4] = {};
    int ksteps = (K + 15) >> 4;
    for (int kt = 0; kt < ksteps; kt++) {
        int k0 = kt * 16;
        #pragma unroll
        for (int l = 0; l < 4; l++) {
            int e = t + l * 256;
            int kk = e & 15, i = e >> 4;
            int gr = m0 + i, gk = k0 + kk;
            As[kk][i] = (gr < M && gk < K) ? A[(size_t)gr * lda + gk] : 0.f;
            int j = e & 63, kb = e >> 6;
            int gk2 = k0 + kb, gn = n0 + j;
            Bs[kb][j] = (gk2 < K && gn < N) ? Bm[(size_t)gk2 * ldb + gn] : 0.f;
        }
        __syncthreads();
        #pragma unroll
        for (int kk = 0; kk < 16; kk++) {
            float4 a4 = *(const float4*)&As[kk][ty * 4];
            float4 b4 = *(const float4*)&Bs[kk][tx * 4];
            float a[4] = {a4.x, a4.y, a4.z, a4.w};
            float b[4] = {b4.x, b4.y, b4.z, b4.w};
            #pragma unroll
            for (int r = 0; r < 4; r++)
                #pragma unroll
                for (int c = 0; c < 4; c++) acc[r][c] += a[r] * b[c];
        }
        __syncthreads();
    }
    #pragma unroll
    for (int r = 0; r < 4; r++) {
        int gr = m0 + ty * 4 + r;
        if (gr >= M) continue;
        #pragma unroll
        for (int c = 0; c < 4; c++) {
            int gn = n0 + tx * 4 + c;
            if (gn < N) Ct[(size_t)gn * ldc + gr] = acc[r][c];
        }
    }
}

// ---------------- folded bias kernel ----------------
__global__ void biasfold_kernel(const float* __restrict__ bp, const float* __restrict__ Win,
                                const float* __restrict__ b_in, const float* __restrict__ bout,
                                const float* __restrict__ Wo, const float* __restrict__ bo,
                                float* __restrict__ bpqkv, float* __restrict__ bco) {
    int j = blockIdx.x;
    int t = threadIdx.x;   // 64
    float s = 0.f;
    if (j < 3 * NA) {
        for (int a = t; a < NA; a += 64) s += bp[a] * Win[(size_t)a * (3 * NA) + j];
    } else {
        int jj = j - 3 * NA;
        for (int a = t; a < NA; a += 64) s += bout[a] * Wo[(size_t)a * ND + jj];
    }
    #pragma unroll
    for (int o = 16; o; o >>= 1) s += __shfl_xor_sync(0xffffffffu, s, o);
    __shared__ float w2[2];
    if ((t & 31) == 0) w2[t >> 5] = s;
    __syncthreads();
    if (t == 0) {
        float tot = w2[0] + w2[1];
        if (j < 3 * NA) bpqkv[j] = tot + b_in[j];
        else bco[j - 3 * NA] = tot + bo[j - 3 * NA];
    }
}

// =====================================================================
// tf32 MMA GEMM mainloop: C = A*B^T + bias.  rnd!=0 -> output rounded
// to tf32 (for operands consumed by downstream tf32 MMAs).
// =====================================================================
__device__ __forceinline__ void projTF32_body(
    const float* __restrict__ A, const float* __restrict__ B,
    const float* __restrict__ bias, float* __restrict__ C,
    int M, int N, int K, int lda, int ldb, int ldc,
    int m0, int n0, int rnd,
    unsigned As[2][16][132], unsigned Bs[2][16][68])
{
    int t = threadIdx.x, lane = t & 31, w = t >> 5;
    int wm = w & 3, wn = w >> 2;
    int arow = t >> 2, akq = (t & 3) * 4;
    const float* Ap0 = A + (size_t)(m0 + arow) * lda + akq;
    const float* Ap1 = Ap0 + (size_t)64 * lda;
    bool bok = (n0 + arow) < N;
    const float* Bp = B + (size_t)(n0 + arow) * ldb + akq;

    float4 aR0, aR1, bR;
    aR0 = *(const float4*)Ap0;
    aR1 = *(const float4*)Ap1;
    bR = bok ? *(const float4*)Bp : make_float4(0.f, 0.f, 0.f, 0.f);
    {
        float av0[4] = {aR0.x, aR0.y, aR0.z, aR0.w};
        float av1[4] = {aR1.x, aR1.y, aR1.z, aR1.w};
        float bv[4]  = {bR.x, bR.y, bR.z, bR.w};
        #pragma unroll
        for (int j = 0; j < 4; j++) {
            As[0][akq + j][arow]      = f2tf(av0[j]);
            As[0][akq + j][arow + 64] = f2tf(av1[j]);
            Bs[0][akq + j][arow]      = f2tf(bv[j]);
        }
    }
    __syncthreads();

    float acc[2][4][4] = {};
    int ksteps = K >> 4;
    int buf = 0;
    for (int kt = 0; kt < ksteps; kt++) {
        bool has_next = (kt + 1 < ksteps);
        if (has_next) {
            int k0 = (kt + 1) << 4;
            aR0 = *(const float4*)(Ap0 + k0);
            aR1 = *(const float4*)(Ap1 + k0);
            bR  = bok ? *(const float4*)(Bp + k0) : make_float4(0.f, 0.f, 0.f, 0.f);
        }
        #pragma unroll
        for (int k8 = 0; k8 < 2; k8++) {
            int kb = k8 * 8 + (lane & 3);
            unsigned af[2][4], bf[4][2];
            #pragma unroll
            for (int mi = 0; mi < 2; mi++) {
                int r0 = wm * 32 + mi * 16 + (lane >> 2);
                af[mi][0] = As[buf][kb][r0];
                af[mi][1] = As[buf][kb][r0 + 8];
                af[mi][2] = As[buf][kb + 4][r0];
                af[mi][3] = As[buf][kb + 4][r0 + 8];
            }
            #pragma unroll
            for (int ni = 0; ni < 4; ni++) {
                int c0 = wn * 32 + ni * 8 + (lane >> 2);
                bf[ni][0] = Bs[buf][kb][c0];
                bf[ni][1] = Bs[buf][kb + 4][c0];
            }
            #pragma unroll
            for (int mi = 0; mi < 2; mi++)
                #pragma unroll
                for (int ni = 0; ni < 4; ni++)
                    mma_tf32(acc[mi][ni], af[mi], bf[ni]);
        }
        if (has_next) {
            int nxt = buf ^ 1;
            float av0[4] = {aR0.x, aR0.y, aR0.z, aR0.w};
            float av1[4] = {aR1.x, aR1.y, aR1.z, aR1.w};
            float bv[4]  = {bR.x, bR.y, bR.z, bR.w};
            #pragma unroll
            for (int j = 0; j < 4; j++) {
                As[nxt][akq + j][arow]      = f2tf(av0[j]);
                As[nxt][akq + j][arow + 64] = f2tf(av1[j]);
                Bs[nxt][akq + j][arow]      = f2tf(bv[j]);
            }
            __syncthreads();
            buf = nxt;
        }
    }
    #pragma unroll
    for (int mi = 0; mi < 2; mi++) {
        #pragma unroll
        for (int ni = 0; ni < 4; ni++) {
            int r = m0 + wm * 32 + mi * 16 + (lane >> 2);
            int c = n0 + wn * 32 + ni * 8 + 2 * (lane & 3);
            if (c < N) {
                float b0v = bias ? bias[c] : 0.f;
                float b1v = bias ? bias[c + 1] : 0.f;
                float o00 = acc[mi][ni][0] + b0v;
                float o01 = acc[mi][ni][1] + b1v;
                float o10 = acc[mi][ni][2] + b0v;
                float o11 = acc[mi][ni][3] + b1v;
                if (rnd) {
                    o00 = UF(f2tf(o00)); o01 = UF(f2tf(o01));
                    o10 = UF(f2tf(o10)); o11 = UF(f2tf(o11));
                }
                C[(size_t)r * ldc + c]           = o00;
                C[(size_t)r * ldc + c + 1]       = o01;
                C[(size_t)(r + 8) * ldc + c]     = o10;
                C[(size_t)(r + 8) * ldc + c + 1] = o11;
            }
        }
    }
}

__global__ __launch_bounds__(256)
void projTF32_kernel(const float* __restrict__ A, const float* __restrict__ B,
                     const float* __restrict__ bias, float* __restrict__ C,
                     int M, int N, int K, int lda, int ldb, int ldc, int rnd) {
    __shared__ unsigned As[2][16][132];
    __shared__ unsigned Bs[2][16][68];
    projTF32_body(A, B, bias, C, M, N, K, lda, ldb, ldc,
                  blockIdx.y * 128, blockIdx.x * 64, rnd, As, Bs);
}

// z-batched variant: z=0 QH(F), z=1 NEWKH(NEWK), z=2 NEWVH(NEWV); all rounded.
__global__ __launch_bounds__(256)
void projTF32z_kernel(const float* __restrict__ A0, const float* __restrict__ A1,
                      const float* __restrict__ A2, const float* __restrict__ Bbase,
                      const float* __restrict__ biasBase, float* __restrict__ Cbase) {
    __shared__ unsigned As[2][16][132];
    __shared__ unsigned Bs[2][16][68];
    int z = blockIdx.z;
    const float* A = (z == 0) ? A0 : ((z == 1) ? A1 : A2);
    projTF32_body(A, Bbase + (size_t)z * NA * ND, biasBase + (size_t)z * NA,
                  Cbase + (size_t)z * NB * NA,
                  NB, NA, ND, ND, ND, NA,
                  blockIdx.y * 128, blockIdx.x * 64, 1, As, Bs);
}

// =====================================================================
// Single-tf32 d2min: rows = mem_keys, cols = features.
// =====================================================================
__global__ __launch_bounds__(256)
void d2minTF_kernel(const float* __restrict__ Km, const float* __restrict__ F,
                    const float* __restrict__ fn2, const float* __restrict__ kn2,
                    unsigned* __restrict__ mind2) {
    __shared__ unsigned As[2][16][132];
    __shared__ unsigned Bs[2][16][68];
    __shared__ float red[4][64];
    int t = threadIdx.x, lane = t & 31, w = t >> 5;
    int wm = w & 3, wn = w >> 2;
    int m0 = blockIdx.y * 128, n0 = blockIdx.x * 64;
    int arow = t >> 2, akq = (t & 3) * 4;
    const float* Ap0 = Km + (size_t)(m0 + arow) * ND + akq;
    const float* Ap1 = Ap0 + (size_t)64 * ND;
    const float* Bp  = F + (size_t)(n0 + arow) * ND + akq;

    float4 aR0 = *(const float4*)Ap0;
    float4 aR1 = *(const float4*)Ap1;
    float4 bR  = *(const float4*)Bp;
    {
        float av0[4] = {aR0.x, aR0.y, aR0.z, aR0.w};
        float av1[4] = {aR1.x, aR1.y, aR1.z, aR1.w};
        float bv[4]  = {bR.x, bR.y, bR.z, bR.w};
        #pragma unroll
        for (int j = 0; j < 4; j++) {
            As[0][akq + j][arow]      = f2tf(av0[j]);
            As[0][akq + j][arow + 64] = f2tf(av1[j]);
            Bs[0][akq + j][arow]      = f2tf(bv[j]);
        }
    }
    __syncthreads();

    float acc[2][4][4] = {};
    int buf = 0;
    for (int kt = 0; kt < ND / 16; kt++) {
        bool has_next = (kt + 1 < ND / 16);
        if (has_next) {
            int k0 = (kt + 1) << 4;
            aR0 = *(const float4*)(Ap0 + k0);
            aR1 = *(const float4*)(Ap1 + k0);
            bR  = *(const float4*)(Bp + k0);
        }
        #pragma unroll
        for (int k8 = 0; k8 < 2; k8++) {
            int kb = k8 * 8 + (lane & 3);
            unsigned af[2][4], bf[4][2];
            #pragma unroll
            for (int mi = 0; mi < 2; mi++) {
                int r0 = wm * 32 + mi * 16 + (lane >> 2);
                af[mi][0] = As[buf][kb][r0];
                af[mi][1] = As[buf][kb][r0 + 8];
                af[mi][2] = As[buf][kb + 4][r0];
                af[mi][3] = As[buf][kb + 4][r0 + 8];
            }
            #pragma unroll
            for (int ni = 0; ni < 4; ni++) {
                int c0 = wn * 32 + ni * 8 + (lane >> 2);
                bf[ni][0] = Bs[buf][kb][c0];
                bf[ni][1] = Bs[buf][kb + 4][c0];
            }
            #pragma unroll
            for (int mi = 0; mi < 2; mi++)
                #pragma unroll
                for (int ni = 0; ni < 4; ni++)
                    mma_tf32(acc[mi][ni], af[mi], bf[ni]);
        }
        if (has_next) {
            int nxt = buf ^ 1;
            float av0[4] = {aR0.x, aR0.y, aR0.z, aR0.w};
            float av1[4] = {aR1.x, aR1.y, aR1.z, aR1.w};
            float bv[4]  = {bR.x, bR.y, bR.z, bR.w};
            #pragma unroll
            for (int j = 0; j < 4; j++) {
                As[nxt][akq + j][arow]      = f2tf(av0[j]);
                As[nxt][akq + j][arow + 64] = f2tf(av1[j]);
                Bs[nxt][akq + j][arow]      = f2tf(bv[j]);
            }
            __syncthreads();
            buf = nxt;
        }
    }

    float kna[2][2];
    #pragma unroll
    for (int mi = 0; mi < 2; mi++)
        #pragma unroll
        for (int hh = 0; hh < 2; hh++)
            kna[mi][hh] = kn2[m0 + wm * 32 + mi * 16 + (lane >> 2) + hh * 8];

    #pragma unroll
    for (int ni = 0; ni < 4; ni++) {
        #pragma unroll
        for (int j = 0; j < 2; j++) {
            float v = 3.4e38f;
            #pragma unroll
            for (int mi = 0; mi < 2; mi++) {
                v = fminf(v, kna[mi][0] - 2.f * acc[mi][ni][j]);
                v = fminf(v, kna[mi][1] - 2.f * acc[mi][ni][2 + j]);
            }
            #pragma unroll
            for (int o = 4; o <= 16; o <<= 1) v = fminf(v, __shfl_xor_sync(0xffffffffu, v, o));
            if (lane < 4) red[wm][wn * 32 + ni * 8 + 2 * lane + j] = v;
        }
    }
    __syncthreads();
    if (t < 64) {
        float v = fminf(fminf(red[0][t], red[1][t]), fminf(red[2][t], red[3][t]));
        atomicMin(&mind2[n0 + t], fenc(fn2[n0 + t] + v));
    }
}

// ---------------- sort + exact sequential eviction simulation ----------------
__global__ void sortsim_kernel(const float* __restrict__ msur, const float* __restrict__ mages,
                               const float* __restrict__ surp) {
    extern __shared__ ull sdyn[];
    ull* keys = sdyn;
    ull* ins  = sdyn + NM;
    float* ssurp = (float*)(ins + 512);
    int* smemz   = (int*)(ssurp + 512);
    __shared__ int s_nw;
    int tid = threadIdx.x;

    for (int i = tid; i < NM; i += 1024) {
        float sc = msur[i] * powf(0.95f, mages[i]);
        keys[i] = ((ull)__float_as_uint(sc) << 32) | (unsigned)i;
    }
    if (tid < 512) {
        ssurp[tid] = surp[tid];
        smemz[tid] = g_ibuf[IB_MEMZ + tid];
    }
    __syncthreads();

    for (unsigned k = 2; k <= NM; k <<= 1) {
        for (unsigned j = k >> 1; j > 0; j >>= 1) {
            for (unsigned base = 0; base < NM; base += 1024) {
                unsigned i = base + tid;
                unsigned p = i ^ j;
                if (p > i) {
                    ull a = keys[i], b = keys[p];
                    bool asc = ((i & k) == 0);
                    if ((a > b) == asc) { keys[i] = b; keys[p] = a; }
                }
            }
            __syncthreads();
        }
    }

    if (tid == 0) {
        int p = 0, insN = 0, nw = 0;
        ull ins_min = ~0ULL; int ins_pos = -1;
        for (int b = 0; b < NB; b++) {
            if (!smemz[b]) continue;
            ull head = keys[p];
            bool fromhead = (head <= ins_min);
            ull cand = fromhead ? head : ins_min;
            int slot = (int)(unsigned)(cand & 0xFFFFFFFFull);
            g_ibuf[IB_WSLOT + nw] = slot;
            g_ibuf[IB_WB + nw] = b;
            nw++;
            ull nk = ((ull)__float_as_uint(ssurp[b]) << 32) | (unsigned)slot;
            if (fromhead) {
                p++;
                ins[insN] = nk;
                if (nk < ins_min) { ins_min = nk; ins_pos = insN; }
                insN++;
            } else {
                ins[ins_pos] = nk;
                ins_min = ~0ULL; ins_pos = -1;
                for (int q2 = 0; q2 < insN; q2++)
                    if (ins[q2] < ins_min) { ins_min = ins[q2]; ins_pos = q2; }
            }
        }
        g_ibuf[IB_NW] = nw;
        s_nw = nw;
    }
    __syncthreads();
    int nw = s_nw;
    for (int i = tid; i < nw; i += 1024) {
        int sl = g_ibuf[IB_WSLOT + i];
        int fin = 1;
        for (int j = i + 1; j < nw; j++)
            if (g_ibuf[IB_WSLOT + j] == sl) { fin = 0; break; }
        g_ibuf[IB_WFIN + i] = fin;
    }
}

// patch written rows of KH/VH with pre-projected new rows
__global__ void scatter_kh_kernel(const float* __restrict__ nkh, const float* __restrict__ nvh,
                                  float* __restrict__ kh, float* __restrict__ vh) {
    int i = blockIdx.x;
    if (i >= g_ibuf[IB_NW] || !g_ibuf[IB_WFIN + i]) return;
    int slot = g_ibuf[IB_WSLOT + i];
    int b = g_ibuf[IB_WB + i];
    for (int j = threadIdx.x; j < NA; j += blockDim.x) {
        kh[(size_t)slot * NA + j] = nkh[(size_t)b * NA + j];
        vh[(size_t)slot * NA + j] = nvh[(size_t)b * NA + j];
    }
}

// =====================================================================
// Single-tf32 flash attention: warp-fragment softmax, register rmax/rsum,
// V-fill REPOSITIONED after the QK^T MMA phase so its LDG latency hides
// under compute (B0 waits only on the K half; V visible by B1 < use at PV).
// 53.5 KB smem, NSPLIT=8 -> 512 blocks = 1 wave.
// =====================================================================
__global__ __launch_bounds__(256)
void attnTF_kernel(const float* __restrict__ qh, const float* __restrict__ kh,
                   const float* __restrict__ vh, float* __restrict__ po,
                   float* __restrict__ pm, float* __restrict__ pl) {
    extern __shared__ float dsm[];
    float* Qs  = dsm;              // [40][68]
    float* Ks  = Qs + 40 * 68;     // [40][68]
    float* Vs  = Ks + 40 * 68;     // [64][52]
    float* STS = Vs + 64 * 52;     // [64 q][68 m] P (tf32)
    float* mx2 = STS + 64 * 68;    // [64][2]
    float* sm2 = mx2 + 128;        // [64][2]

    int t = threadIdx.x, lane = t & 31, w = t >> 5;
    int wq = w & 3, wn = w >> 2;
    int b0 = blockIdx.x * 64, h = blockIdx.y, split = blockIdx.z;

    for (int i = t; i < 40 * 68; i += 256) { Qs[i] = 0.f; Ks[i] = 0.f; }
    for (int i = t; i < 64 * 52; i += 256) Vs[i] = 0.f;
    __syncthreads();
    for (int e = t; e < 64 * 33; e += 256) {
        int r = e / 33, d = e - r * 33;
        Qs[d * 68 + r] = qh[(size_t)(b0 + r) * NA + h * 33 + d];
    }
    float rmax0 = -3.0e38f, rmax1 = -3.0e38f;
    float rsum0 = 0.f, rsum1 = 0.f;
    float accO[3][4] = {};
    __syncthreads();

    const float SCL = ATT_SC * L2E;
    int r0 = wq * 16 + (lane >> 2);
    int lc = lane & 3;
    int m_base = split * (NM / NSPLIT);
    for (int ch = 0; ch < (NM / NSPLIT) / 64; ch++) {
        int m0 = m_base + ch * 64;
        // ---- K fill only (V fill moved after QK) ----
        for (int e = t; e < 64 * 33; e += 256) {
            int r = e / 33, d = e - r * 33;
            Ks[d * 68 + r] = kh[(size_t)(m0 + r) * NA + h * 33 + d];
        }
        __syncthreads();                          // B0: K visible

        // ---- S = Q·K^T (registers only) ----
        float accS[4][4] = {};
        #pragma unroll
        for (int kd = 0; kd < 5; kd++) {
            int kb = kd * 8 + lc;
            unsigned a[4] = {FU(Qs[kb * 68 + r0]), FU(Qs[kb * 68 + r0 + 8]),
                             FU(Qs[(kb + 4) * 68 + r0]), FU(Qs[(kb + 4) * 68 + r0 + 8])};
            #pragma unroll
            for (int ni = 0; ni < 4; ni++) {
                int c0 = wn * 32 + ni * 8 + (lane >> 2);
                unsigned b[2] = {FU(Ks[kb * 68 + c0]), FU(Ks[(kb + 4) * 68 + c0])};
                mma_tf32(accS[ni], a, b);
            }
        }

        // ---- V fill (LDG latency overlapped by the MMAs above; visible at B1,
        //      consumed after B2) ----
        for (int e = t; e < 64 * 33; e += 256) {
            int r = e / 33, d = e - r * 33;
            Vs[r * 52 + d] = vh[(size_t)(m0 + r) * NA + h * 33 + d];
        }

        // ---- warp-fragment row max (half-row per warp) ----
        {
            float m0v = -3.0e38f, m1v = -3.0e38f;
            #pragma unroll
            for (int ni = 0; ni < 4; ni++) {
                m0v = fmaxf(m0v, fmaxf(accS[ni][0], accS[ni][1]));
                m1v = fmaxf(m1v, fmaxf(accS[ni][2], accS[ni][3]));
            }
            m0v = fmaxf(m0v, __shfl_xor_sync(0xffffffffu, m0v, 1));
            m0v = fmaxf(m0v, __shfl_xor_sync(0xffffffffu, m0v, 2));
            m1v = fmaxf(m1v, __shfl_xor_sync(0xffffffffu, m1v, 1));
            m1v = fmaxf(m1v, __shfl_xor_sync(0xffffffffu, m1v, 2));
            if (lc == 0) {
                mx2[r0 * 2 + wn] = m0v * ATT_SC;
                mx2[(r0 + 8) * 2 + wn] = m1v * ATT_SC;
            }
        }
        __syncthreads();                          // B1: mx2 + Vs visible

        // ---- redundant per-thread alpha/rmax update (registers) ----
        float alpha0, alpha1;
        {
            float cm0 = fmaxf(mx2[r0 * 2], mx2[r0 * 2 + 1]);
            float nm0 = fmaxf(rmax0, cm0);
            alpha0 = exp2f((rmax0 - nm0) * L2E);
            rmax0 = nm0;
            float cm1 = fmaxf(mx2[(r0 + 8) * 2], mx2[(r0 + 8) * 2 + 1]);
            float nm1 = fmaxf(rmax1, cm1);
            alpha1 = exp2f((rmax1 - nm1) * L2E);
            rmax1 = nm1;
        }

        // ---- exp in registers + P store + half-row sums ----
        {
            float rl0 = rmax0 * L2E, rl1 = rmax1 * L2E;
            float s0 = 0.f, s1 = 0.f;
            #pragma unroll
            for (int ni = 0; ni < 4; ni++) {
                float p00 = exp2f(accS[ni][0] * SCL - rl0);
                float p01 = exp2f(accS[ni][1] * SCL - rl0);
                float p10 = exp2f(accS[ni][2] * SCL - rl1);
                float p11 = exp2f(accS[ni][3] * SCL - rl1);
                s0 += p00 + p01;
                s1 += p10 + p11;
                int c = wn * 32 + ni * 8 + 2 * lc;
                *(float2*)&STS[r0 * 68 + c] = make_float2(UF(f2tf(p00)), UF(f2tf(p01)));
                *(float2*)&STS[(r0 + 8) * 68 + c] = make_float2(UF(f2tf(p10)), UF(f2tf(p11)));
            }
            s0 += __shfl_xor_sync(0xffffffffu, s0, 1);
            s0 += __shfl_xor_sync(0xffffffffu, s0, 2);
            s1 += __shfl_xor_sync(0xffffffffu, s1, 1);
            s1 += __shfl_xor_sync(0xffffffffu, s1, 2);
            if (lc == 0) {
                sm2[r0 * 2 + wn] = s0;
                sm2[(r0 + 8) * 2 + wn] = s1;
            }
        }
        __syncthreads();                          // B2: P + sm2 visible

        // ---- redundant rsum update (registers) ----
        rsum0 = rsum0 * alpha0 + (sm2[r0 * 2] + sm2[r0 * 2 + 1]);
        rsum1 = rsum1 * alpha1 + (sm2[(r0 + 8) * 2] + sm2[(r0 + 8) * 2 + 1]);

        // ---- rescale + P·V ----
        #pragma unroll
        for (int ni = 0; ni < 3; ni++) {
            accO[ni][0] *= alpha0; accO[ni][1] *= alpha0;
            accO[ni][2] *= alpha1; accO[ni][3] *= alpha1;
        }
        #pragma unroll
        for (int ks = 0; ks < 8; ks++) {
            int kb = ks * 8 + lc;
            unsigned a[4] = {FU(STS[r0 * 68 + kb]), FU(STS[(r0 + 8) * 68 + kb]),
                             FU(STS[r0 * 68 + kb + 4]), FU(STS[(r0 + 8) * 68 + kb + 4])};
            #pragma unroll
            for (int ni = 0; ni < 3; ni++) {
                int c0 = wn * 24 + ni * 8 + (lane >> 2);
                unsigned b[2] = {FU(Vs[kb * 52 + c0]), FU(Vs[(kb + 4) * 52 + c0])};
                mma_tf32(accO[ni], a, b);
            }
        }
        __syncthreads();                          // B3: end of chunk (K/V/P reuse)
    }

    {
        size_t row0 = (size_t)(split * NB + b0 + r0) * NA + h * 33;
        size_t row1 = (size_t)(split * NB + b0 + r0 + 8) * NA + h * 33;
        #pragma unroll
        for (int ni = 0; ni < 3; ni++) {
            int c = wn * 24 + ni * 8 + 2 * lc;
            if (c < 33)     { po[row0 + c]     = accO[ni][0]; po[row1 + c]     = accO[ni][2]; }
            if (c + 1 < 33) { po[row0 + c + 1] = accO[ni][1]; po[row1 + c + 1] = accO[ni][3]; }
        }
    }
    if (wn == 0 && lc == 0) {
        size_t i0 = (size_t)(split * NB + b0 + r0) * NH + h;
        size_t i1 = (size_t)(split * NB + b0 + r0 + 8) * NH + h;
        pm[i0] = rmax0; pl[i0] = rsum0;
        pm[i1] = rmax1; pl[i1] = rsum1;
    }
}

__global__ void merge_kernel(const float* __restrict__ po, const float* __restrict__ pm,
                             const float* __restrict__ pl, float* __restrict__ ctx) {
    int b = blockIdx.x;
    int d = threadIdx.x;   // 272
    if (d >= NA) { ctx[(size_t)b * CTXLD + d] = 0.f; return; }
    int h = d / 33;
    float M = -3.0e38f;
    float pmv[NSPLIT];
    #pragma unroll
    for (int s = 0; s < NSPLIT; s++) {
        pmv[s] = pm[(size_t)(s * NB + b) * NH + h];
        M = fmaxf(M, pmv[s]);
    }
    float num = 0.f, den = 0.f;
    #pragma unroll
    for (int s = 0; s < NSPLIT; s++) {
        float wgt = exp2f((pmv[s] - M) * L2E);
        num += po[(size_t)(s * NB + b) * NA + d] * wgt;
        den += pl[(size_t)(s * NB + b) * NH + h] * wgt;
    }
    ctx[(size_t)b * CTXLD + d] = num / den;
}

// ---------------- one-time stream/event setup ----------------
static cudaStream_t g_s1;
static cudaEvent_t g_evRoot, g_evFold, g_evKV, g_evWCOT;
static bool g_init_done = false;

// ---------------- launch ----------------
extern "C" void kernel_launch(void* const* d_in, const int* in_sizes, int n_in,
                              void* d_out, int out_size) {
    const float* F    = (const float*)d_in[0];
    const float* G    = (const float*)d_in[1];
    const float* MK   = (const float*)d_in[2];
    const float* MV   = (const float*)d_in[3];
    const float* AGES = (const float*)d_in[4];
    const float* MS   = (const float*)d_in[5];
    const float* Wk   = (const float*)d_in[6];
    const float* bk   = (const float*)d_in[7];
    const float* Wv   = (const float*)d_in[8];
    const float* bv   = (const float*)d_in[9];
    const float* Wp   = (const float*)d_in[10];
    const float* bp   = (const float*)d_in[11];
    const float* Win  = (const float*)d_in[12];
    const float* b_in = (const float*)d_in[13];
    const float* Wout = (const float*)d_in[14];
    const float* bout = (const float*)d_in[15];
    const float* Wo   = (const float*)d_in[16];
    const float* bo   = (const float*)d_in[17];
    float* out = (float*)d_out;

    float* fb = nullptr;
    cudaGetSymbolAddress((void**)&fb, g_fbuf);
    int* ib = nullptr;
    cudaGetSymbolAddress((void**)&ib, g_ibuf);

    float* KH = fb + O_KH;
    float* VH = fb + O_VH;
    float* PO = fb + O_PO;
    float* NEWK = fb + O_NEWK;
    float* NEWV = fb + O_NEWV;
    float* QH = fb + O_QH;
    float* NEWKH = fb + O_NEWKH;
    float* NEWVH = fb + O_NEWVH;
    float* WPQT = fb + O_FOLD;
    float* WPKT = WPQT + (size_t)NA * ND;
    float* WPVT = WPKT + (size_t)NA * ND;
    float* WKT = fb + O_WKT;
    float* WVT = fb + O_WVT;
    float* WCOT = fb + O_WCOT;
    float* CTX = fb + O_CTX;
    float* BPQ = fb + O_BPQ;
    float* BCO = fb + O_BCO;
    float* FN2 = fb + O_FN2;
    float* GN2 = fb + O_GN2;
    float* KN2 = fb + O_KN2;
    unsigned* MIND2 = (unsigned*)(fb + O_MIND2);
    float* SURP = fb + O_SURP;
    float* PM = fb + O_PM;
    float* PL = fb + O_PL;

    if (!g_init_done) {
        cudaFuncSetAttribute(sortsim_kernel, cudaFuncAttributeMaxDynamicSharedMemorySize, 160000);
        cudaFuncSetAttribute(attnTF_kernel, cudaFuncAttributeMaxDynamicSharedMemorySize, 56320);
        cudaStreamCreateWithFlags(&g_s1, cudaStreamNonBlocking);
        cudaEventCreateWithFlags(&g_evRoot, cudaEventDisableTiming);
        cudaEventCreateWithFlags(&g_evFold, cudaEventDisableTiming);
        cudaEventCreateWithFlags(&g_evKV, cudaEventDisableTiming);
        cudaEventCreateWithFlags(&g_evWCOT, cudaEventDisableTiming);
        g_init_done = true;
    }
    cudaStream_t s1 = g_s1;

    cudaEventRecord(g_evRoot, 0);
    cudaStreamWaitEvent(s1, g_evRoot, 0);

    dim3 tb16(16, 16);
    dim3 tt(32, 8);

    // ======== side stream: fold -> KH -> VH (evKV) -> WCOT (evWCOT) ========
    biasfold_kernel<<<3 * NA + ND, 64, 0, s1>>>(bp, Win, b_in, bout, Wo, bo, BPQ, BCO);
    gemmT_kernel<<<dim3(13, 4), tb16, 0, s1>>>(Wp, Win, WPQT, ND, 3 * NA, NA, NA, 3 * NA, ND);
    cudaEventRecord(g_evFold, s1);
    projTF32_kernel<<<dim3(5, NM / 128), 256, 0, s1>>>(MK, WPKT, BPQ + NA,     KH, NM, NA, ND, ND, ND, NA, 1);
    projTF32_kernel<<<dim3(5, NM / 128), 256, 0, s1>>>(MV, WPVT, BPQ + 2 * NA, VH, NM, NA, ND, ND, ND, NA, 1);
    cudaEventRecord(g_evKV, s1);
    zero_kernel<<<(ND * CTXLD + 255) / 256, 256, 0, s1>>>(WCOT, ND * CTXLD);
    gemmT_kernel<<<dim3(4, 5), tb16, 0, s1>>>(Wout, Wo, WCOT, NA, ND, NA, NA, ND, CTXLD);
    cudaEventRecord(g_evWCOT, s1);

    // ======== main stream: NEWK/NEWV + batched projections + surprise ========
    {
        dim3 tgD(8, 8);
        transpose_kernel<<<tgD, tt>>>(Wk, WKT, ND, ND, ND);
        transpose_kernel<<<tgD, tt>>>(Wv, WVT, ND, ND, ND);
    }
    projTF32_kernel<<<dim3(4, 4), 256>>>(F, WKT, bk, NEWK, NB, ND, ND, ND, ND, ND, 0);
    projTF32_kernel<<<dim3(4, 4), 256>>>(F, WVT, bv, NEWV, NB, ND, ND, ND, ND, ND, 0);
    cudaStreamWaitEvent((cudaStream_t)0, g_evFold, 0);
    projTF32z_kernel<<<dim3(5, 4, 3), 256>>>(F, NEWK, NEWV, WPQT, BPQ, QH);
    rownorm2_kernel<<<NB, ND>>>(F, FN2);
    rownorm2_kernel<<<NB, ND>>>(G, GN2);
    rownorm2_kernel<<<NM, ND>>>(MK, KN2);
    init_kernel<<<2, 256>>>(MIND2);
    d2minTF_kernel<<<dim3(NB / 64, NM / 128), 256>>>(MK, F, FN2, KN2, MIND2);
    surprise_kernel<<<2, 256>>>(MIND2, GN2, SURP, ib + IB_MEMZ);
    sortsim_kernel<<<1, 1024, 139264>>>(MS, AGES, SURP);

    // join: patch + attention (waits only KH/VH), output proj waits WCOT
    cudaStreamWaitEvent((cudaStream_t)0, g_evKV, 0);
    scatter_kh_kernel<<<NB, 128>>>(NEWKH, NEWVH, KH, VH);
    attnTF_kernel<<<dim3(NB / 64, NH, NSPLIT), 256, 53504>>>(QH, KH, VH, PO, PM, PL);
    merge_kernel<<<NB, CTXLD>>>(PO, PM, PL, CTX);
    cudaStreamWaitEvent((cudaStream_t)0, g_evWCOT, 0);
    projTF32_kernel<<<dim3(4, 4), 256>>>(CTX, WCOT, BCO, out, NB, ND, CTXLD, CTXLD, CTXLD, ND, 0);
}

// round 17
// speedup vs baseline: 1.0387x; 1.0387x over previous
#include <cuda_runtime.h>
#include <math.h>
#include <stdint.h>

#define NB 512
#define ND 256
#define NA 264
#define NM 16384
#define NH 8
#define NHD 33
#define NSPLIT 8
#define ATT_SC 0.17407765595569785f   // 1/sqrt(33)
#define L2E 1.4426950408889634f
#define CTXLD 272

typedef unsigned long long ull;

// ---------------- scratch ----------------
constexpr size_t SZ_MA   = (size_t)NM * NA;
constexpr size_t O_KH    = 0;
constexpr size_t O_VH    = O_KH + SZ_MA;
constexpr size_t O_PO    = O_VH + SZ_MA;
constexpr size_t O_NEWK  = O_PO + (size_t)NSPLIT * NB * NA;
constexpr size_t O_NEWV  = O_NEWK + (size_t)NB * ND;
constexpr size_t O_QH    = O_NEWV + (size_t)NB * ND;        // QH, NEWKH, NEWVH contiguous
constexpr size_t O_NEWKH = O_QH + (size_t)NB * NA;
constexpr size_t O_NEWVH = O_NEWKH + (size_t)NB * NA;
constexpr size_t O_FOLD  = O_NEWVH + (size_t)NB * NA;       // [792][256] fold^T
constexpr size_t O_WKT   = O_FOLD + (size_t)3 * NA * ND;
constexpr size_t O_WVT   = O_WKT + (size_t)ND * ND;
constexpr size_t O_WCOT  = O_WVT + (size_t)ND * ND;         // [256][272]
constexpr size_t O_CTX   = O_WCOT + (size_t)ND * CTXLD;
constexpr size_t O_BPQ   = O_CTX + (size_t)NB * CTXLD;
constexpr size_t O_BCO   = O_BPQ + 3 * NA;
constexpr size_t O_FN2   = O_BCO + ND;
constexpr size_t O_GN2   = O_FN2 + NB;
constexpr size_t O_KN2   = O_GN2 + NB;
constexpr size_t O_MIND2 = O_KN2 + NM;
constexpr size_t O_SURP  = O_MIND2 + NB;
constexpr size_t O_PM    = O_SURP + NB;
constexpr size_t O_PL    = O_PM + (size_t)NSPLIT * NB * NH;
constexpr size_t O_END   = O_PL + (size_t)NSPLIT * NB * NH;

__device__ float g_fbuf[O_END];

#define IB_MEMZ  0
#define IB_NW    512
#define IB_WSLOT 520
#define IB_WB    1036
#define IB_WFIN  1552
__device__ int g_ibuf[2072];

// ---------------- helpers ----------------
__device__ __forceinline__ unsigned fenc(float f) {
    unsigned b = __float_as_uint(f);
    return b ^ (unsigned)(((int)b >> 31) | 0x80000000);
}
__device__ __forceinline__ float fdec(unsigned e) {
    unsigned b = (e & 0x80000000u) ? (e ^ 0x80000000u) : ~e;
    return __uint_as_float(b);
}
__device__ __forceinline__ unsigned f2tf(float x) {
    unsigned r;
    asm("cvt.rna.tf32.f32 %0, %1;" : "=r"(r) : "f"(x));
    return r;
}
__device__ __forceinline__ void mma_tf32(float d[4], const unsigned a[4], const unsigned b[2]) {
    asm volatile("mma.sync.aligned.m16n8k8.row.col.f32.tf32.tf32.f32 "
                 "{%0,%1,%2,%3}, {%4,%5,%6,%7}, {%8,%9}, {%0,%1,%2,%3};\n"
                 : "+f"(d[0]), "+f"(d[1]), "+f"(d[2]), "+f"(d[3])
                 : "r"(a[0]), "r"(a[1]), "r"(a[2]), "r"(a[3]), "r"(b[0]), "r"(b[1]));
}
#define UF(x) __uint_as_float(x)
#define FU(x) __float_as_uint(x)

// ---------------- small kernels ----------------
__global__ void init_kernel(unsigned* mind2) {
    int i = blockIdx.x * 256 + threadIdx.x;
    if (i < NB) mind2[i] = 0xFFFFFFFFu;
}
__global__ void zero_kernel(float* p, int n) {
    int i = blockIdx.x * 256 + threadIdx.x;
    if (i < n) p[i] = 0.f;
}
// fused F+G row-norms: blocks [0,NB) -> F/fn2, [NB,2NB) -> G/gn2
__global__ void rownorm2FG_kernel(const float* __restrict__ F, const float* __restrict__ G,
                                  float* __restrict__ fn2, float* __restrict__ gn2) {
    int blk = blockIdx.x;
    const float* X = (blk < NB) ? F : G;
    float* out = (blk < NB) ? fn2 : gn2;
    int row = (blk < NB) ? blk : blk - NB;
    int t = threadIdx.x;
    float v = X[(size_t)row * ND + t];
    float s = v * v;
    #pragma unroll
    for (int o = 16; o; o >>= 1) s += __shfl_xor_sync(0xffffffffu, s, o);
    __shared__ float ws[8];
    if ((t & 31) == 0) ws[t >> 5] = s;
    __syncthreads();
    if (t == 0) {
        float tot = 0.f;
        #pragma unroll
        for (int i = 0; i < 8; i++) tot += ws[i];
        out[row] = tot;
    }
}
__global__ void rownorm2_kernel(const float* __restrict__ X, float* __restrict__ out) {
    int row = blockIdx.x;
    int t = threadIdx.x;
    float v = X[(size_t)row * ND + t];
    float s = v * v;
    #pragma unroll
    for (int o = 16; o; o >>= 1) s += __shfl_xor_sync(0xffffffffu, s, o);
    __shared__ float ws[8];
    if ((t & 31) == 0) ws[t >> 5] = s;
    __syncthreads();
    if (t == 0) {
        float tot = 0.f;
        #pragma unroll
        for (int i = 0; i < 8; i++) tot += ws[i];
        out[row] = tot;
    }
}
__global__ void surprise_kernel(const unsigned* __restrict__ mind2,
                                const float* __restrict__ gn2,
                                float* __restrict__ surp, int* __restrict__ memz) {
    int b = blockIdx.x * 256 + threadIdx.x;
    if (b < NB) {
        float md2 = fdec(mind2[b]);
        if (md2 < 0.f) md2 = 0.f;
        float s = sqrtf(gn2[b]) * sqrtf(md2);
        surp[b] = s;
        memz[b] = (s > 0.1f) ? 1 : 0;
    }
}
__global__ void transpose_kernel(const float* __restrict__ src, float* __restrict__ dst,
                                 int R, int C, int ldd) {
    __shared__ float tile[32][33];
    int x = blockIdx.x * 32 + threadIdx.x;
    int y = blockIdx.y * 32 + threadIdx.y;
    #pragma unroll
    for (int j = 0; j < 32; j += 8)
        if (y + j < R && x < C) tile[threadIdx.y + j][threadIdx.x] = src[(size_t)(y + j) * C + x];
    __syncthreads();
    int x2 = blockIdx.y * 32 + threadIdx.x;
    int y2 = blockIdx.x * 32 + threadIdx.y;
    #pragma unroll
    for (int j = 0; j < 32; j += 8)
        if (y2 + j < C && x2 < R) dst[(size_t)(y2 + j) * ldd + x2] = tile[threadIdx.x][threadIdx.y + j];
}

// ---------------- legacy SGEMM with TRANSPOSED store ----------------
__global__ __launch_bounds__(256)
void gemmT_kernel(const float* __restrict__ A, const float* __restrict__ Bm,
                  float* __restrict__ Ct,
                  int M, int N, int K, int lda, int ldb, int ldc) {
    __shared__ __align__(16) float As[16][68];
    __shared__ __align__(16) float Bs[16][68];
    int tx = threadIdx.x, ty = threadIdx.y;
    int t = ty * 16 + tx;
    int m0 = blockIdx.y * 64, n0 = blockIdx.x * 64;
    float acc[4][4] = {};
    int ksteps = (K + 15) >> 4;
    for (int kt = 0; kt < ksteps; kt++) {
        int k0 = kt * 16;
        #pragma unroll
        for (int l = 0; l < 4; l++) {
            int e = t + l * 256;
            int kk = e & 15, i = e >> 4;
            int gr = m0 + i, gk = k0 + kk;
            As[kk][i] = (gr < M && gk < K) ? A[(size_t)gr * lda + gk] : 0.f;
            int j = e & 63, kb = e >> 6;
            int gk2 = k0 + kb, gn = n0 + j;
            Bs[kb][j] = (gk2 < K && gn < N) ? Bm[(size_t)gk2 * ldb + gn] : 0.f;
        }
        __syncthreads();
        #pragma unroll
        for (int kk = 0; kk < 16; kk++) {
            float4 a4 = *(const float4*)&As[kk][ty * 4];
            float4 b4 = *(const float4*)&Bs[kk][tx * 4];
            float a[4] = {a4.x, a4.y, a4.z, a4.w};
            float b[4] = {b4.x, b4.y, b4.z, b4.w};
            #pragma unroll
            for (int r = 0; r < 4; r++)
                #pragma unroll
                for (int c = 0; c < 4; c++) acc[r][c] += a[r] * b[c];
        }
        __syncthreads();
    }
    #pragma unroll
    for (int r = 0; r < 4; r++) {
        int gr = m0 + ty * 4 + r;
        if (gr >= M) continue;
        #pragma unroll
        for (int c = 0; c < 4; c++) {
            int gn = n0 + tx * 4 + c;
            if (gn < N) Ct[(size_t)gn * ldc + gr] = acc[r][c];
        }
    }
}

// ---------------- folded bias kernel ----------------
__global__ void biasfold_kernel(const float* __restrict__ bp, const float* __restrict__ Win,
                                const float* __restrict__ b_in, const float* __restrict__ bout,
                                const float* __restrict__ Wo, const float* __restrict__ bo,
                                float* __restrict__ bpqkv, float* __restrict__ bco) {
    int j = blockIdx.x;
    int t = threadIdx.x;   // 64
    float s = 0.f;
    if (j < 3 * NA) {
        for (int a = t; a < NA; a += 64) s += bp[a] * Win[(size_t)a * (3 * NA) + j];
    } else {
        int jj = j - 3 * NA;
        for (int a = t; a < NA; a += 64) s += bout[a] * Wo[(size_t)a * ND + jj];
    }
    #pragma unroll
    for (int o = 16; o; o >>= 1) s += __shfl_xor_sync(0xffffffffu, s, o);
    __shared__ float w2[2];
    if ((t & 31) == 0) w2[t >> 5] = s;
    __syncthreads();
    if (t == 0) {
        float tot = w2[0] + w2[1];
        if (j < 3 * NA) bpqkv[j] = tot + b_in[j];
        else bco[j - 3 * NA] = tot + bo[j - 3 * NA];
    }
}

// =====================================================================
// tf32 MMA GEMM mainloop: C = A*B^T + bias.  rnd!=0 -> output rounded
// to tf32 (for operands consumed by downstream tf32 MMAs).
// =====================================================================
__device__ __forceinline__ void projTF32_body(
    const float* __restrict__ A, const float* __restrict__ B,
    const float* __restrict__ bias, float* __restrict__ C,
    int M, int N, int K, int lda, int ldb, int ldc,
    int m0, int n0, int rnd,
    unsigned As[2][16][132], unsigned Bs[2][16][68])
{
    int t = threadIdx.x, lane = t & 31, w = t >> 5;
    int wm = w & 3, wn = w >> 2;
    int arow = t >> 2, akq = (t & 3) * 4;
    const float* Ap0 = A + (size_t)(m0 + arow) * lda + akq;
    const float* Ap1 = Ap0 + (size_t)64 * lda;
    bool bok = (n0 + arow) < N;
    const float* Bp = B + (size_t)(n0 + arow) * ldb + akq;

    float4 aR0, aR1, bR;
    aR0 = *(const float4*)Ap0;
    aR1 = *(const float4*)Ap1;
    bR = bok ? *(const float4*)Bp : make_float4(0.f, 0.f, 0.f, 0.f);
    {
        float av0[4] = {aR0.x, aR0.y, aR0.z, aR0.w};
        float av1[4] = {aR1.x, aR1.y, aR1.z, aR1.w};
        float bv[4]  = {bR.x, bR.y, bR.z, bR.w};
        #pragma unroll
        for (int j = 0; j < 4; j++) {
            As[0][akq + j][arow]      = f2tf(av0[j]);
            As[0][akq + j][arow + 64] = f2tf(av1[j]);
            Bs[0][akq + j][arow]      = f2tf(bv[j]);
        }
    }
    __syncthreads();

    float acc[2][4][4] = {};
    int ksteps = K >> 4;
    int buf = 0;
    for (int kt = 0; kt < ksteps; kt++) {
        bool has_next = (kt + 1 < ksteps);
        if (has_next) {
            int k0 = (kt + 1) << 4;
            aR0 = *(const float4*)(Ap0 + k0);
            aR1 = *(const float4*)(Ap1 + k0);
            bR  = bok ? *(const float4*)(Bp + k0) : make_float4(0.f, 0.f, 0.f, 0.f);
        }
        #pragma unroll
        for (int k8 = 0; k8 < 2; k8++) {
            int kb = k8 * 8 + (lane & 3);
            unsigned af[2][4], bf[4][2];
            #pragma unroll
            for (int mi = 0; mi < 2; mi++) {
                int r0 = wm * 32 + mi * 16 + (lane >> 2);
                af[mi][0] = As[buf][kb][r0];
                af[mi][1] = As[buf][kb][r0 + 8];
                af[mi][2] = As[buf][kb + 4][r0];
                af[mi][3] = As[buf][kb + 4][r0 + 8];
            }
            #pragma unroll
            for (int ni = 0; ni < 4; ni++) {
                int c0 = wn * 32 + ni * 8 + (lane >> 2);
                bf[ni][0] = Bs[buf][kb][c0];
                bf[ni][1] = Bs[buf][kb + 4][c0];
            }
            #pragma unroll
            for (int mi = 0; mi < 2; mi++)
                #pragma unroll
                for (int ni = 0; ni < 4; ni++)
                    mma_tf32(acc[mi][ni], af[mi], bf[ni]);
        }
        if (has_next) {
            int nxt = buf ^ 1;
            float av0[4] = {aR0.x, aR0.y, aR0.z, aR0.w};
            float av1[4] = {aR1.x, aR1.y, aR1.z, aR1.w};
            float bv[4]  = {bR.x, bR.y, bR.z, bR.w};
            #pragma unroll
            for (int j = 0; j < 4; j++) {
                As[nxt][akq + j][arow]      = f2tf(av0[j]);
                As[nxt][akq + j][arow + 64] = f2tf(av1[j]);
                Bs[nxt][akq + j][arow]      = f2tf(bv[j]);
            }
            __syncthreads();
            buf = nxt;
        }
    }
    #pragma unroll
    for (int mi = 0; mi < 2; mi++) {
        #pragma unroll
        for (int ni = 0; ni < 4; ni++) {
            int r = m0 + wm * 32 + mi * 16 + (lane >> 2);
            int c = n0 + wn * 32 + ni * 8 + 2 * (lane & 3);
            if (c < N) {
                float b0v = bias ? bias[c] : 0.f;
                float b1v = bias ? bias[c + 1] : 0.f;
                float o00 = acc[mi][ni][0] + b0v;
                float o01 = acc[mi][ni][1] + b1v;
                float o10 = acc[mi][ni][2] + b0v;
                float o11 = acc[mi][ni][3] + b1v;
                if (rnd) {
                    o00 = UF(f2tf(o00)); o01 = UF(f2tf(o01));
                    o10 = UF(f2tf(o10)); o11 = UF(f2tf(o11));
                }
                C[(size_t)r * ldc + c]           = o00;
                C[(size_t)r * ldc + c + 1]       = o01;
                C[(size_t)(r + 8) * ldc + c]     = o10;
                C[(size_t)(r + 8) * ldc + c + 1] = o11;
            }
        }
    }
}

__global__ __launch_bounds__(256)
void projTF32_kernel(const float* __restrict__ A, const float* __restrict__ B,
                     const float* __restrict__ bias, float* __restrict__ C,
                     int M, int N, int K, int lda, int ldb, int ldc, int rnd) {
    __shared__ unsigned As[2][16][132];
    __shared__ unsigned Bs[2][16][68];
    projTF32_body(A, B, bias, C, M, N, K, lda, ldb, ldc,
                  blockIdx.y * 128, blockIdx.x * 64, rnd, As, Bs);
}

// z-batched variant: z=0 QH(F), z=1 NEWKH(NEWK), z=2 NEWVH(NEWV); all rounded.
__global__ __launch_bounds__(256)
void projTF32z_kernel(const float* __restrict__ A0, const float* __restrict__ A1,
                      const float* __restrict__ A2, const float* __restrict__ Bbase,
                      const float* __restrict__ biasBase, float* __restrict__ Cbase) {
    __shared__ unsigned As[2][16][132];
    __shared__ unsigned Bs[2][16][68];
    int z = blockIdx.z;
    const float* A = (z == 0) ? A0 : ((z == 1) ? A1 : A2);
    projTF32_body(A, Bbase + (size_t)z * NA * ND, biasBase + (size_t)z * NA,
                  Cbase + (size_t)z * NB * NA,
                  NB, NA, ND, ND, ND, NA,
                  blockIdx.y * 128, blockIdx.x * 64, 1, As, Bs);
}

// =====================================================================
// Single-tf32 d2min: rows = mem_keys, cols = features.
// =====================================================================
__global__ __launch_bounds__(256)
void d2minTF_kernel(const float* __restrict__ Km, const float* __restrict__ F,
                    const float* __restrict__ fn2, const float* __restrict__ kn2,
                    unsigned* __restrict__ mind2) {
    __shared__ unsigned As[2][16][132];
    __shared__ unsigned Bs[2][16][68];
    __shared__ float red[4][64];
    int t = threadIdx.x, lane = t & 31, w = t >> 5;
    int wm = w & 3, wn = w >> 2;
    int m0 = blockIdx.y * 128, n0 = blockIdx.x * 64;
    int arow = t >> 2, akq = (t & 3) * 4;
    const float* Ap0 = Km + (size_t)(m0 + arow) * ND + akq;
    const float* Ap1 = Ap0 + (size_t)64 * ND;
    const float* Bp  = F + (size_t)(n0 + arow) * ND + akq;

    float4 aR0 = *(const float4*)Ap0;
    float4 aR1 = *(const float4*)Ap1;
    float4 bR  = *(const float4*)Bp;
    {
        float av0[4] = {aR0.x, aR0.y, aR0.z, aR0.w};
        float av1[4] = {aR1.x, aR1.y, aR1.z, aR1.w};
        float bv[4]  = {bR.x, bR.y, bR.z, bR.w};
        #pragma unroll
        for (int j = 0; j < 4; j++) {
            As[0][akq + j][arow]      = f2tf(av0[j]);
            As[0][akq + j][arow + 64] = f2tf(av1[j]);
            Bs[0][akq + j][arow]      = f2tf(bv[j]);
        }
    }
    __syncthreads();

    float acc[2][4][4] = {};
    int buf = 0;
    for (int kt = 0; kt < ND / 16; kt++) {
        bool has_next = (kt + 1 < ND / 16);
        if (has_next) {
            int k0 = (kt + 1) << 4;
            aR0 = *(const float4*)(Ap0 + k0);
            aR1 = *(const float4*)(Ap1 + k0);
            bR  = *(const float4*)(Bp + k0);
        }
        #pragma unroll
        for (int k8 = 0; k8 < 2; k8++) {
            int kb = k8 * 8 + (lane & 3);
            unsigned af[2][4], bf[4][2];
            #pragma unroll
            for (int mi = 0; mi < 2; mi++) {
                int r0 = wm * 32 + mi * 16 + (lane >> 2);
                af[mi][0] = As[buf][kb][r0];
                af[mi][1] = As[buf][kb][r0 + 8];
                af[mi][2] = As[buf][kb + 4][r0];
                af[mi][3] = As[buf][kb + 4][r0 + 8];
            }
            #pragma unroll
            for (int ni = 0; ni < 4; ni++) {
                int c0 = wn * 32 + ni * 8 + (lane >> 2);
                bf[ni][0] = Bs[buf][kb][c0];
                bf[ni][1] = Bs[buf][kb + 4][c0];
            }
            #pragma unroll
            for (int mi = 0; mi < 2; mi++)
                #pragma unroll
                for (int ni = 0; ni < 4; ni++)
                    mma_tf32(acc[mi][ni], af[mi], bf[ni]);
        }
        if (has_next) {
            int nxt = buf ^ 1;
            float av0[4] = {aR0.x, aR0.y, aR0.z, aR0.w};
            float av1[4] = {aR1.x, aR1.y, aR1.z, aR1.w};
            float bv[4]  = {bR.x, bR.y, bR.z, bR.w};
            #pragma unroll
            for (int j = 0; j < 4; j++) {
                As[nxt][akq + j][arow]      = f2tf(av0[j]);
                As[nxt][akq + j][arow + 64] = f2tf(av1[j]);
                Bs[nxt][akq + j][arow]      = f2tf(bv[j]);
            }
            __syncthreads();
            buf = nxt;
        }
    }

    float kna[2][2];
    #pragma unroll
    for (int mi = 0; mi < 2; mi++)
        #pragma unroll
        for (int hh = 0; hh < 2; hh++)
            kna[mi][hh] = kn2[m0 + wm * 32 + mi * 16 + (lane >> 2) + hh * 8];

    #pragma unroll
    for (int ni = 0; ni < 4; ni++) {
        #pragma unroll
        for (int j = 0; j < 2; j++) {
            float v = 3.4e38f;
            #pragma unroll
            for (int mi = 0; mi < 2; mi++) {
                v = fminf(v, kna[mi][0] - 2.f * acc[mi][ni][j]);
                v = fminf(v, kna[mi][1] - 2.f * acc[mi][ni][2 + j]);
            }
            #pragma unroll
            for (int o = 4; o <= 16; o <<= 1) v = fminf(v, __shfl_xor_sync(0xffffffffu, v, o));
            if (lane < 4) red[wm][wn * 32 + ni * 8 + 2 * lane + j] = v;
        }
    }
    __syncthreads();
    if (t < 64) {
        float v = fminf(fminf(red[0][t], red[1][t]), fminf(red[2][t], red[3][t]));
        atomicMin(&mind2[n0 + t], fenc(fn2[n0 + t] + v));
    }
}

// ---------------- sort + exact sequential eviction simulation ----------------
__global__ void sortsim_kernel(const float* __restrict__ msur, const float* __restrict__ mages,
                               const float* __restrict__ surp) {
    extern __shared__ ull sdyn[];
    ull* keys = sdyn;
    ull* ins  = sdyn + NM;
    float* ssurp = (float*)(ins + 512);
    int* smemz   = (int*)(ssurp + 512);
    __shared__ int s_nw;
    int tid = threadIdx.x;

    for (int i = tid; i < NM; i += 1024) {
        float sc = msur[i] * powf(0.95f, mages[i]);
        keys[i] = ((ull)__float_as_uint(sc) << 32) | (unsigned)i;
    }
    if (tid < 512) {
        ssurp[tid] = surp[tid];
        smemz[tid] = g_ibuf[IB_MEMZ + tid];
    }
    __syncthreads();

    for (unsigned k = 2; k <= NM; k <<= 1) {
        for (unsigned j = k >> 1; j > 0; j >>= 1) {
            for (unsigned base = 0; base < NM; base += 1024) {
                unsigned i = base + tid;
                unsigned p = i ^ j;
                if (p > i) {
                    ull a = keys[i], b = keys[p];
                    bool asc = ((i & k) == 0);
                    if ((a > b) == asc) { keys[i] = b; keys[p] = a; }
                }
            }
            __syncthreads();
        }
    }

    if (tid == 0) {
        int p = 0, insN = 0, nw = 0;
        ull ins_min = ~0ULL; int ins_pos = -1;
        for (int b = 0; b < NB; b++) {
            if (!smemz[b]) continue;
            ull head = keys[p];
            bool fromhead = (head <= ins_min);
            ull cand = fromhead ? head : ins_min;
            int slot = (int)(unsigned)(cand & 0xFFFFFFFFull);
            g_ibuf[IB_WSLOT + nw] = slot;
            g_ibuf[IB_WB + nw] = b;
            nw++;
            ull nk = ((ull)__float_as_uint(ssurp[b]) << 32) | (unsigned)slot;
            if (fromhead) {
                p++;
                ins[insN] = nk;
                if (nk < ins_min) { ins_min = nk; ins_pos = insN; }
                insN++;
            } else {
                ins[ins_pos] = nk;
                ins_min = ~0ULL; ins_pos = -1;
                for (int q2 = 0; q2 < insN; q2++)
                    if (ins[q2] < ins_min) { ins_min = ins[q2]; ins_pos = q2; }
            }
        }
        g_ibuf[IB_NW] = nw;
        s_nw = nw;
    }
    __syncthreads();
    int nw = s_nw;
    for (int i = tid; i < nw; i += 1024) {
        int sl = g_ibuf[IB_WSLOT + i];
        int fin = 1;
        for (int j = i + 1; j < nw; j++)
            if (g_ibuf[IB_WSLOT + j] == sl) { fin = 0; break; }
        g_ibuf[IB_WFIN + i] = fin;
    }
}

// patch written rows of KH/VH with pre-projected new rows
__global__ void scatter_kh_kernel(const float* __restrict__ nkh, const float* __restrict__ nvh,
                                  float* __restrict__ kh, float* __restrict__ vh) {
    int i = blockIdx.x;
    if (i >= g_ibuf[IB_NW] || !g_ibuf[IB_WFIN + i]) return;
    int slot = g_ibuf[IB_WSLOT + i];
    int b = g_ibuf[IB_WB + i];
    for (int j = threadIdx.x; j < NA; j += blockDim.x) {
        kh[(size_t)slot * NA + j] = nkh[(size_t)b * NA + j];
        vh[(size_t)slot * NA + j] = nvh[(size_t)b * NA + j];
    }
}

// =====================================================================
// Single-tf32 flash attention (R15 structure: combined K/V fill, warp-
// fragment softmax, register rmax/rsum; 4 barriers/chunk).
// 53.5 KB smem, NSPLIT=8 -> 512 blocks = 1 wave.
// =====================================================================
__global__ __launch_bounds__(256)
void attnTF_kernel(const float* __restrict__ qh, const float* __restrict__ kh,
                   const float* __restrict__ vh, float* __restrict__ po,
                   float* __restrict__ pm, float* __restrict__ pl) {
    extern __shared__ float dsm[];
    float* Qs  = dsm;              // [40][68]
    float* Ks  = Qs + 40 * 68;     // [40][68]
    float* Vs  = Ks + 40 * 68;     // [64][52]
    float* STS = Vs + 64 * 52;     // [64 q][68 m] P (tf32)
    float* mx2 = STS + 64 * 68;    // [64][2]
    float* sm2 = mx2 + 128;        // [64][2]

    int t = threadIdx.x, lane = t & 31, w = t >> 5;
    int wq = w & 3, wn = w >> 2;
    int b0 = blockIdx.x * 64, h = blockIdx.y, split = blockIdx.z;

    for (int i = t; i < 40 * 68; i += 256) { Qs[i] = 0.f; Ks[i] = 0.f; }
    for (int i = t; i < 64 * 52; i += 256) Vs[i] = 0.f;
    __syncthreads();
    for (int e = t; e < 64 * 33; e += 256) {
        int r = e / 33, d = e - r * 33;
        Qs[d * 68 + r] = qh[(size_t)(b0 + r) * NA + h * 33 + d];
    }
    float rmax0 = -3.0e38f, rmax1 = -3.0e38f;
    float rsum0 = 0.f, rsum1 = 0.f;
    float accO[3][4] = {};
    __syncthreads();

    const float SCL = ATT_SC * L2E;
    int r0 = wq * 16 + (lane >> 2);
    int lc = lane & 3;
    int m_base = split * (NM / NSPLIT);
    for (int ch = 0; ch < (NM / NSPLIT) / 64; ch++) {
        int m0 = m_base + ch * 64;
        for (int e = t; e < 64 * 33; e += 256) {
            int r = e / 33, d = e - r * 33;
            size_t gi = (size_t)(m0 + r) * NA + h * 33 + d;
            Ks[d * 68 + r] = kh[gi];
            Vs[r * 52 + d] = vh[gi];
        }
        __syncthreads();                          // B0: K/V visible

        // ---- S = Q·K^T (registers only) ----
        float accS[4][4] = {};
        #pragma unroll
        for (int kd = 0; kd < 5; kd++) {
            int kb = kd * 8 + lc;
            unsigned a[4] = {FU(Qs[kb * 68 + r0]), FU(Qs[kb * 68 + r0 + 8]),
                             FU(Qs[(kb + 4) * 68 + r0]), FU(Qs[(kb + 4) * 68 + r0 + 8])};
            #pragma unroll
            for (int ni = 0; ni < 4; ni++) {
                int c0 = wn * 32 + ni * 8 + (lane >> 2);
                unsigned b[2] = {FU(Ks[kb * 68 + c0]), FU(Ks[(kb + 4) * 68 + c0])};
                mma_tf32(accS[ni], a, b);
            }
        }

        // ---- warp-fragment row max (half-row per warp) ----
        {
            float m0v = -3.0e38f, m1v = -3.0e38f;
            #pragma unroll
            for (int ni = 0; ni < 4; ni++) {
                m0v = fmaxf(m0v, fmaxf(accS[ni][0], accS[ni][1]));
                m1v = fmaxf(m1v, fmaxf(accS[ni][2], accS[ni][3]));
            }
            m0v = fmaxf(m0v, __shfl_xor_sync(0xffffffffu, m0v, 1));
            m0v = fmaxf(m0v, __shfl_xor_sync(0xffffffffu, m0v, 2));
            m1v = fmaxf(m1v, __shfl_xor_sync(0xffffffffu, m1v, 1));
            m1v = fmaxf(m1v, __shfl_xor_sync(0xffffffffu, m1v, 2));
            if (lc == 0) {
                mx2[r0 * 2 + wn] = m0v * ATT_SC;
                mx2[(r0 + 8) * 2 + wn] = m1v * ATT_SC;
            }
        }
        __syncthreads();                          // B1: mx2 visible

        // ---- redundant per-thread alpha/rmax update (registers) ----
        float alpha0, alpha1;
        {
            float cm0 = fmaxf(mx2[r0 * 2], mx2[r0 * 2 + 1]);
            float nm0 = fmaxf(rmax0, cm0);
            alpha0 = exp2f((rmax0 - nm0) * L2E);
            rmax0 = nm0;
            float cm1 = fmaxf(mx2[(r0 + 8) * 2], mx2[(r0 + 8) * 2 + 1]);
            float nm1 = fmaxf(rmax1, cm1);
            alpha1 = exp2f((rmax1 - nm1) * L2E);
            rmax1 = nm1;
        }

        // ---- exp in registers + P store + half-row sums ----
        {
            float rl0 = rmax0 * L2E, rl1 = rmax1 * L2E;
            float s0 = 0.f, s1 = 0.f;
            #pragma unroll
            for (int ni = 0; ni < 4; ni++) {
                float p00 = exp2f(accS[ni][0] * SCL - rl0);
                float p01 = exp2f(accS[ni][1] * SCL - rl0);
                float p10 = exp2f(accS[ni][2] * SCL - rl1);
                float p11 = exp2f(accS[ni][3] * SCL - rl1);
                s0 += p00 + p01;
                s1 += p10 + p11;
                int c = wn * 32 + ni * 8 + 2 * lc;
                *(float2*)&STS[r0 * 68 + c] = make_float2(UF(f2tf(p00)), UF(f2tf(p01)));
                *(float2*)&STS[(r0 + 8) * 68 + c] = make_float2(UF(f2tf(p10)), UF(f2tf(p11)));
            }
            s0 += __shfl_xor_sync(0xffffffffu, s0, 1);
            s0 += __shfl_xor_sync(0xffffffffu, s0, 2);
            s1 += __shfl_xor_sync(0xffffffffu, s1, 1);
            s1 += __shfl_xor_sync(0xffffffffu, s1, 2);
            if (lc == 0) {
                sm2[r0 * 2 + wn] = s0;
                sm2[(r0 + 8) * 2 + wn] = s1;
            }
        }
        __syncthreads();                          // B2: P + sm2 visible

        // ---- redundant rsum update (registers) ----
        rsum0 = rsum0 * alpha0 + (sm2[r0 * 2] + sm2[r0 * 2 + 1]);
        rsum1 = rsum1 * alpha1 + (sm2[(r0 + 8) * 2] + sm2[(r0 + 8) * 2 + 1]);

        // ---- rescale + P·V ----
        #pragma unroll
        for (int ni = 0; ni < 3; ni++) {
            accO[ni][0] *= alpha0; accO[ni][1] *= alpha0;
            accO[ni][2] *= alpha1; accO[ni][3] *= alpha1;
        }
        #pragma unroll
        for (int ks = 0; ks < 8; ks++) {
            int kb = ks * 8 + lc;
            unsigned a[4] = {FU(STS[r0 * 68 + kb]), FU(STS[(r0 + 8) * 68 + kb]),
                             FU(STS[r0 * 68 + kb + 4]), FU(STS[(r0 + 8) * 68 + kb + 4])};
            #pragma unroll
            for (int ni = 0; ni < 3; ni++) {
                int c0 = wn * 24 + ni * 8 + (lane >> 2);
                unsigned b[2] = {FU(Vs[kb * 52 + c0]), FU(Vs[(kb + 4) * 52 + c0])};
                mma_tf32(accO[ni], a, b);
            }
        }
        __syncthreads();                          // B3: end of chunk (K/V/P reuse)
    }

    {
        size_t row0 = (size_t)(split * NB + b0 + r0) * NA + h * 33;
        size_t row1 = (size_t)(split * NB + b0 + r0 + 8) * NA + h * 33;
        #pragma unroll
        for (int ni = 0; ni < 3; ni++) {
            int c = wn * 24 + ni * 8 + 2 * lc;
            if (c < 33)     { po[row0 + c]     = accO[ni][0]; po[row1 + c]     = accO[ni][2]; }
            if (c + 1 < 33) { po[row0 + c + 1] = accO[ni][1]; po[row1 + c + 1] = accO[ni][3]; }
        }
    }
    if (wn == 0 && lc == 0) {
        size_t i0 = (size_t)(split * NB + b0 + r0) * NH + h;
        size_t i1 = (size_t)(split * NB + b0 + r0 + 8) * NH + h;
        pm[i0] = rmax0; pl[i0] = rsum0;
        pm[i1] = rmax1; pl[i1] = rsum1;
    }
}

__global__ void merge_kernel(const float* __restrict__ po, const float* __restrict__ pm,
                             const float* __restrict__ pl, float* __restrict__ ctx) {
    int b = blockIdx.x;
    int d = threadIdx.x;   // 272
    if (d >= NA) { ctx[(size_t)b * CTXLD + d] = 0.f; return; }
    int h = d / 33;
    float M = -3.0e38f;
    float pmv[NSPLIT];
    #pragma unroll
    for (int s = 0; s < NSPLIT; s++) {
        pmv[s] = pm[(size_t)(s * NB + b) * NH + h];
        M = fmaxf(M, pmv[s]);
    }
    float num = 0.f, den = 0.f;
    #pragma unroll
    for (int s = 0; s < NSPLIT; s++) {
        float wgt = exp2f((pmv[s] - M) * L2E);
        num += po[(size_t)(s * NB + b) * NA + d] * wgt;
        den += pl[(size_t)(s * NB + b) * NH + h] * wgt;
    }
    ctx[(size_t)b * CTXLD + d] = num / den;
}

// ---------------- one-time stream/event setup ----------------
static cudaStream_t g_s1;
static cudaEvent_t g_evRoot, g_evFold, g_evKV, g_evWCOT;
static bool g_init_done = false;

// ---------------- launch ----------------
extern "C" void kernel_launch(void* const* d_in, const int* in_sizes, int n_in,
                              void* d_out, int out_size) {
    const float* F    = (const float*)d_in[0];
    const float* G    = (const float*)d_in[1];
    const float* MK   = (const float*)d_in[2];
    const float* MV   = (const float*)d_in[3];
    const float* AGES = (const float*)d_in[4];
    const float* MS   = (const float*)d_in[5];
    const float* Wk   = (const float*)d_in[6];
    const float* bk   = (const float*)d_in[7];
    const float* Wv   = (const float*)d_in[8];
    const float* bv   = (const float*)d_in[9];
    const float* Wp   = (const float*)d_in[10];
    const float* bp   = (const float*)d_in[11];
    const float* Win  = (const float*)d_in[12];
    const float* b_in = (const float*)d_in[13];
    const float* Wout = (const float*)d_in[14];
    const float* bout = (const float*)d_in[15];
    const float* Wo   = (const float*)d_in[16];
    const float* bo   = (const float*)d_in[17];
    float* out = (float*)d_out;

    float* fb = nullptr;
    cudaGetSymbolAddress((void**)&fb, g_fbuf);
    int* ib = nullptr;
    cudaGetSymbolAddress((void**)&ib, g_ibuf);

    float* KH = fb + O_KH;
    float* VH = fb + O_VH;
    float* PO = fb + O_PO;
    float* NEWK = fb + O_NEWK;
    float* NEWV = fb + O_NEWV;
    float* QH = fb + O_QH;
    float* NEWKH = fb + O_NEWKH;
    float* NEWVH = fb + O_NEWVH;
    float* WPQT = fb + O_FOLD;
    float* WPKT = WPQT + (size_t)NA * ND;
    float* WPVT = WPKT + (size_t)NA * ND;
    float* WKT = fb + O_WKT;
    float* WVT = fb + O_WVT;
    float* WCOT = fb + O_WCOT;
    float* CTX = fb + O_CTX;
    float* BPQ = fb + O_BPQ;
    float* BCO = fb + O_BCO;
    float* FN2 = fb + O_FN2;
    float* GN2 = fb + O_GN2;
    float* KN2 = fb + O_KN2;
    unsigned* MIND2 = (unsigned*)(fb + O_MIND2);
    float* SURP = fb + O_SURP;
    float* PM = fb + O_PM;
    float* PL = fb + O_PL;

    if (!g_init_done) {
        cudaFuncSetAttribute(sortsim_kernel, cudaFuncAttributeMaxDynamicSharedMemorySize, 160000);
        cudaFuncSetAttribute(attnTF_kernel, cudaFuncAttributeMaxDynamicSharedMemorySize, 56320);
        cudaStreamCreateWithFlags(&g_s1, cudaStreamNonBlocking);
        cudaEventCreateWithFlags(&g_evRoot, cudaEventDisableTiming);
        cudaEventCreateWithFlags(&g_evFold, cudaEventDisableTiming);
        cudaEventCreateWithFlags(&g_evKV, cudaEventDisableTiming);
        cudaEventCreateWithFlags(&g_evWCOT, cudaEventDisableTiming);
        g_init_done = true;
    }
    cudaStream_t s1 = g_s1;

    cudaEventRecord(g_evRoot, 0);
    cudaStreamWaitEvent(s1, g_evRoot, 0);

    dim3 tb16(16, 16);
    dim3 tt(32, 8);

    // ======== side stream: fold -> KH -> VH (evKV) -> WCOT (evWCOT) ========
    biasfold_kernel<<<3 * NA + ND, 64, 0, s1>>>(bp, Win, b_in, bout, Wo, bo, BPQ, BCO);
    gemmT_kernel<<<dim3(13, 4), tb16, 0, s1>>>(Wp, Win, WPQT, ND, 3 * NA, NA, NA, 3 * NA, ND);
    cudaEventRecord(g_evFold, s1);
    projTF32_kernel<<<dim3(5, NM / 128), 256, 0, s1>>>(MK, WPKT, BPQ + NA,     KH, NM, NA, ND, ND, ND, NA, 1);
    projTF32_kernel<<<dim3(5, NM / 128), 256, 0, s1>>>(MV, WPVT, BPQ + 2 * NA, VH, NM, NA, ND, ND, ND, NA, 1);
    cudaEventRecord(g_evKV, s1);
    zero_kernel<<<(ND * CTXLD + 255) / 256, 256, 0, s1>>>(WCOT, ND * CTXLD);
    gemmT_kernel<<<dim3(4, 5), tb16, 0, s1>>>(Wout, Wo, WCOT, NA, ND, NA, NA, ND, CTXLD);
    cudaEventRecord(g_evWCOT, s1);

    // ======== main stream: NEWK/NEWV + surprise path (no mid-stream stall) ========
    {
        dim3 tgD(8, 8);
        transpose_kernel<<<tgD, tt>>>(Wk, WKT, ND, ND, ND);
        transpose_kernel<<<tgD, tt>>>(Wv, WVT, ND, ND, ND);
    }
    projTF32_kernel<<<dim3(4, 4), 256>>>(F, WKT, bk, NEWK, NB, ND, ND, ND, ND, ND, 0);
    projTF32_kernel<<<dim3(4, 4), 256>>>(F, WVT, bv, NEWV, NB, ND, ND, ND, ND, ND, 0);
    rownorm2FG_kernel<<<2 * NB, ND>>>(F, G, FN2, GN2);
    rownorm2_kernel<<<NM, ND>>>(MK, KN2);
    init_kernel<<<2, 256>>>(MIND2);
    d2minTF_kernel<<<dim3(NB / 64, NM / 128), 256>>>(MK, F, FN2, KN2, MIND2);
    surprise_kernel<<<2, 256>>>(MIND2, GN2, SURP, ib + IB_MEMZ);
    sortsim_kernel<<<1, 1024, 139264>>>(MS, AGES, SURP);

    // batched QH / NEWKH / NEWVH after sortsim (fold long since done -> no stall)
    cudaStreamWaitEvent((cudaStream_t)0, g_evFold, 0);
    projTF32z_kernel<<<dim3(5, 4, 3), 256>>>(F, NEWK, NEWV, WPQT, BPQ, QH);

    // join: patch + attention (waits only KH/VH), output proj waits WCOT
    cudaStreamWaitEvent((cudaStream_t)0, g_evKV, 0);
    scatter_kh_kernel<<<NB, 128>>>(NEWKH, NEWVH, KH, VH);
    attnTF_kernel<<<dim3(NB / 64, NH, NSPLIT), 256, 53504>>>(QH, KH, VH, PO, PM, PL);
    merge_kernel<<<NB, CTXLD>>>(PO, PM, PL, CTX);
    cudaStreamWaitEvent((cudaStream_t)0, g_evWCOT, 0);
    projTF32_kernel<<<dim3(4, 4), 256>>>(CTX, WCOT, BCO, out, NB, ND, CTXLD, CTXLD, CTXLD, ND, 0);
}